// round 16
// baseline (speedup 1.0000x reference)
#include <cuda_runtime.h>
#include <cstdint>

#define Bsz 8
#define Nn 1024
#define Ee 256
#define Dm 64
#define Hh 4
#define DH 16

// fold 1/sqrt(64) * log2(e) into gq so scores feed ex2 directly
#define QSCALE 0.180336880520712f

// ---------------- device scratch ----------------
__device__ float d_e [4][Bsz][Hh][Ee][DH];        // eq, ek, ceq, cek
__device__ float d_g [2][2][Bsz][Hh][DH][Nn];     // [branch][q|k][b][h][c][n]
// fused emb->q/k weights: [qk][i][64] at 0/64/128/192, biases [qk][64] at 256/320
__device__ float d_wfold[384];

// ---------------- K1: edge projections + weight folding ----------------
// grid 129 x 256: bid<128 edge rows; bid==128 computes fused q/k weights.
__global__ void __launch_bounds__(256)
k_prep(const float* __restrict__ W_emb, const float* __restrict__ b_emb,
       const float* __restrict__ W_q,   const float* __restrict__ b_q,
       const float* __restrict__ W_k,   const float* __restrict__ b_k,
       const float* __restrict__ edge,  const float* __restrict__ cedge,
       const float* __restrict__ W_eq,  const float* __restrict__ b_eq,
       const float* __restrict__ W_ek,  const float* __restrict__ b_ek,
       const float* __restrict__ W_ceq, const float* __restrict__ b_ceq,
       const float* __restrict__ W_cek, const float* __restrict__ b_cek) {
    int tid = threadIdx.x;

    if (blockIdx.x < 128) {
        __shared__ float sW4[1024];               // [4][16][16]
        __shared__ float sb4[64];                 // [4][16]
        {
            const float* Ws[4] = {W_eq, W_ek, W_ceq, W_cek};
            for (int l = tid; l < 1024; l += 256)
                sW4[l] = Ws[l >> 8][l & 255];
            if (tid < 64) {
                const float* Bs[4] = {b_eq, b_ek, b_ceq, b_cek};
                sb4[tid] = Bs[tid >> 4][tid & 15];
            }
        }
        __syncthreads();

        int i = blockIdx.x * 256 + tid;           // 0..32767
        int t = i >> 13;
        int r = i & 8191;
        const float* src = (t < 2 ? edge : cedge) + r * 16;
        float s[16];
#pragma unroll
        for (int j4 = 0; j4 < 4; ++j4) {
            float4 v = *(const float4*)(src + j4 * 4);
            s[j4 * 4 + 0] = v.x; s[j4 * 4 + 1] = v.y;
            s[j4 * 4 + 2] = v.z; s[j4 * 4 + 3] = v.w;
        }
        float acc[16];
#pragma unroll
        for (int cc = 0; cc < 16; ++cc) acc[cc] = sb4[t * 16 + cc];
#pragma unroll
        for (int j = 0; j < 16; ++j) {
            float sv = s[j];
#pragma unroll
            for (int cc = 0; cc < 16; ++cc)
                acc[cc] = fmaf(sv, sW4[t * 256 + j * 16 + cc], acc[cc]);
        }
        float* dst = (&d_e[0][0][0][0][0]) + (size_t)i * 16;
#pragma unroll
        for (int c4 = 0; c4 < 4; ++c4)
            *(float4*)(dst + c4 * 4) =
                make_float4(acc[c4 * 4], acc[c4 * 4 + 1], acc[c4 * 4 + 2], acc[c4 * 4 + 3]);
    } else {
        __shared__ float sWe[128];
        __shared__ float sbe[64];
        if (tid < 128) sWe[tid] = W_emb[tid];
        if (tid < 64)  sbe[tid] = b_emb[tid];
        __syncthreads();
        int c = tid & 63;
        int role = tid >> 6;                      // 0:(q,i0) 1:(q,i1) 2:(k,i0) 3:(k,i1)
        const float* W = (role < 2) ? W_q : W_k;
        int i = role & 1;
        float acc = 0.f;
#pragma unroll
        for (int j = 0; j < 64; ++j)
            acc = fmaf(sWe[i * 64 + j], W[j * 64 + c], acc);
        d_wfold[(role >> 1) * 128 + i * 64 + c] = acc;
        if ((role & 1) == 0) {
            const float* bb = (role == 0) ? b_q : b_k;
            float bacc = bb[c];
#pragma unroll
            for (int j = 0; j < 64; ++j)
                bacc = fmaf(sbe[j], W[j * 64 + c], bacc);
            d_wfold[256 + (role >> 1) * 64 + c] = bacc;
        }
    }
}

// ---------------- K3 v4: gq/gk + div — 32-n tiles, 2 n/thread, 4 CTA/SM ----------------
// grid per branch: 8b * 32nt = 256 blocks; 256 threads = 16 c x 16 ns (2 n each).
__global__ void __launch_bounds__(256, 4)
k_gextra(const float* __restrict__ G, const float* __restrict__ CG,
         const float* __restrict__ x, int br) {
    int bid = blockIdx.x;
    int nt = bid & 31;  bid >>= 5;
    int b  = bid & 7;
    int tid = threadIdx.x;
    int c  = tid >> 4;          // 0..15
    int ns = tid & 15;          // 0..15 -> n = nbase + ns*2 + {0,1}
    int nbase = nt * 32;

    const float* Gm  = (br ? CG : G) + (size_t)b * Ee * Nn;
    const float* eqb = &d_e[br * 2 + 0][b][0][0][0];   // [h][e][c], h-stride 4096
    const float* ekb = &d_e[br * 2 + 1][b][0][0][0];

    __shared__ float2 sg2[16][16];       // [ee][ns]  16e x 32n
    __shared__ float  seq[4][16][16];    // [h][ee][c]  = 256 float4
    __shared__ float  sek[4][16][16];
    __shared__ float  swf[384];          // fused weights + biases
    __shared__ float  sx[64];            // x[b][nbase..nbase+31][2]
    float4* sq4 = (float4*)&seq[0][0][0];
    float4* sk4 = (float4*)&sek[0][0][0];

    if (tid < 64) sx[tid] = x[((size_t)b * Nn + nbase) * 2 + tid];
    for (int i = tid; i < 384; i += 256) swf[i] = d_wfold[i];

    // staging index split
    int ge = tid >> 4, gn = tid & 15;                       // G: one float2/thread
    int h4 = tid >> 6, ee4 = (tid & 63) >> 2, c4 = tid & 3; // e-proj: one float4/thread
    const float* gsrc = Gm + (size_t)ge * Nn + nbase + gn * 2;
    size_t eoff = (size_t)(h4 * Ee + ee4) * DH + c4 * 4;

    float aq[4][2], ak[4][2];            // [h][n]
#pragma unroll
    for (int h = 0; h < 4; ++h)
#pragma unroll
        for (int j = 0; j < 2; ++j) { aq[h][j] = 0.f; ak[h][j] = 0.f; }
    float gs0 = 0.f, gs1 = 0.f;

    // preload tile 0
    float2 gpre = *(const float2*)(gsrc);
    float4 qpre = *(const float4*)(eqb + eoff);
    float4 kpre = *(const float4*)(ekb + eoff);

#pragma unroll 1
    for (int e0 = 0; e0 < Ee; e0 += 16) {
        sg2[ge][gn] = gpre;
        sq4[tid] = qpre;
        sk4[tid] = kpre;
        __syncthreads();
        if (e0 + 16 < Ee) {              // prefetch next tile
            gpre = *(const float2*)(gsrc + (size_t)(e0 + 16) * Nn);
            qpre = *(const float4*)(eqb + eoff + (size_t)(e0 + 16) * DH);
            kpre = *(const float4*)(ekb + eoff + (size_t)(e0 + 16) * DH);
        }
#pragma unroll
        for (int ee = 0; ee < 16; ++ee) {
            float2 g = sg2[ee][ns];
            gs0 += g.x; gs1 += g.y;
#pragma unroll
            for (int h = 0; h < 4; ++h) {
                float eqv = seq[h][ee][c];
                float ekv = sek[h][ee][c];
                aq[h][0] = fmaf(g.x, eqv, aq[h][0]);
                aq[h][1] = fmaf(g.y, eqv, aq[h][1]);
                ak[h][0] = fmaf(g.x, ekv, ak[h][0]);
                ak[h][1] = fmaf(g.y, ekv, ak[h][1]);
            }
        }
        __syncthreads();
    }
    float rd0 = 1.0f / gs0, rd1 = 1.0f / gs1;
    int n0 = nbase + ns * 2;

    float x00 = sx[(ns * 2 + 0) * 2 + 0], x01 = sx[(ns * 2 + 0) * 2 + 1];
    float x10 = sx[(ns * 2 + 1) * 2 + 0], x11 = sx[(ns * 2 + 1) * 2 + 1];
#pragma unroll
    for (int h = 0; h < 4; ++h) {
        int ch = h * 16 + c;
        float wq0 = swf[ch],       wq1 = swf[64 + ch];
        float wk0 = swf[128 + ch], wk1 = swf[192 + ch];
        float bq  = swf[256 + ch], bk  = swf[320 + ch];
        float2 oq, ok;
        oq.x = (fmaf(x00, wq0, fmaf(x01, wq1, bq)) + aq[h][0] * rd0) * QSCALE;
        oq.y = (fmaf(x10, wq0, fmaf(x11, wq1, bq)) + aq[h][1] * rd1) * QSCALE;
        ok.x = (fmaf(x00, wk0, fmaf(x01, wk1, bk)) + ak[h][0] * rd0);
        ok.y = (fmaf(x10, wk0, fmaf(x11, wk1, bk)) + ak[h][1] * rd1);
        *(float2*)&d_g[br][0][b][h][c][n0] = oq;
        *(float2*)&d_g[br][1][b][h][c][n0] = ok;
    }
}

// ---------------- K4: scores + softmax — per-branch grid (UNCHANGED body) ----------------
#define RCHUNK 32
__global__ void __launch_bounds__(256, 2)
k_attn(float* __restrict__ out, int br) {
    int bid = blockIdx.x;
    int chunk = bid & 31;  bid >>= 5;
    int h     = bid & 3;   bid >>= 2;
    int b     = bid & 7;
    int rbase = chunk * RCHUNK;

    const float* gq = &d_g[br][0][b][h][0][0];   // [c][n]
    const float* gk = &d_g[br][1][b][h][0][0];   // [c][n]

    __shared__ float sq[RCHUNK][20];
    __shared__ float spart[2][8][4];             // parity double-buffered

    int tid  = threadIdx.x;
    int warp = tid >> 5, lane = tid & 31;
    int col0 = warp * 128 + lane * 4;

    float4 kk[16];
#pragma unroll
    for (int c = 0; c < 16; ++c)
        kk[c] = *(const float4*)(gk + c * Nn + col0);

    for (int i = tid; i < RCHUNK * 16; i += 256) {
        int c = i >> 5, r = i & 31;
        sq[r][c] = gq[c * Nn + rbase + r];
    }
    __syncthreads();

    size_t obase = ((((size_t)br * Bsz + b) * Hh + h) * Nn + rbase) * (size_t)Nn;

#pragma unroll 1
    for (int wv = 0; wv < RCHUNK / 4; ++wv) {
        int r0 = wv * 4;
        float4 ex[4];
        float part[4];
#pragma unroll
        for (int rr = 0; rr < 4; ++rr) {
            const float* qp = &sq[r0 + rr][0];
            float4 qa = *(const float4*)(qp + 0);
            float4 qb = *(const float4*)(qp + 4);
            float4 qc = *(const float4*)(qp + 8);
            float4 qd = *(const float4*)(qp + 12);
            float qv[16] = {qa.x, qa.y, qa.z, qa.w, qb.x, qb.y, qb.z, qb.w,
                            qc.x, qc.y, qc.z, qc.w, qd.x, qd.y, qd.z, qd.w};
            float s0 = 0.f, s1 = 0.f, s2 = 0.f, s3 = 0.f;
#pragma unroll
            for (int c = 0; c < 16; ++c) {
                s0 = fmaf(qv[c], kk[c].x, s0);
                s1 = fmaf(qv[c], kk[c].y, s1);
                s2 = fmaf(qv[c], kk[c].z, s2);
                s3 = fmaf(qv[c], kk[c].w, s3);
            }
            float e0, e1, e2, e3;
            asm("ex2.approx.f32 %0, %1;" : "=f"(e0) : "f"(s0));
            asm("ex2.approx.f32 %0, %1;" : "=f"(e1) : "f"(s1));
            asm("ex2.approx.f32 %0, %1;" : "=f"(e2) : "f"(s2));
            asm("ex2.approx.f32 %0, %1;" : "=f"(e3) : "f"(s3));
            ex[rr] = make_float4(e0, e1, e2, e3);
            part[rr] = (e0 + e1) + (e2 + e3);
        }
#pragma unroll
        for (int o = 16; o; o >>= 1)
#pragma unroll
            for (int rr = 0; rr < 4; ++rr)
                part[rr] += __shfl_xor_sync(0xffffffffu, part[rr], o);
        int par = wv & 1;
        if (lane == 0) {
#pragma unroll
            for (int rr = 0; rr < 4; ++rr) spart[par][warp][rr] = part[rr];
        }
        __syncthreads();                         // single barrier per wave
#pragma unroll
        for (int rr = 0; rr < 4; ++rr) {
            float v = spart[par][lane & 7][rr];  // 8-way broadcast LDS
            v += __shfl_xor_sync(0xffffffffu, v, 1);
            v += __shfl_xor_sync(0xffffffffu, v, 2);
            v += __shfl_xor_sync(0xffffffffu, v, 4);
            float iv = 1.0f / v;
            float4 o4 = ex[rr];
            o4.x *= iv; o4.y *= iv; o4.z *= iv; o4.w *= iv;
            __stcs((float4*)(out + obase + (size_t)(r0 + rr) * Nn + col0), o4);
        }
    }
}

// ---------------- launcher: dual-stream branch pipeline ----------------
extern "C" void kernel_launch(void* const* d_in, const int* in_sizes, int n_in,
                              void* d_out, int out_size) {
    const float* x      = (const float*)d_in[0];
    const float* edge   = (const float*)d_in[1];
    const float* cedge  = (const float*)d_in[2];
    const float* G      = (const float*)d_in[3];
    const float* CG     = (const float*)d_in[4];
    const float* W_emb  = (const float*)d_in[5];
    const float* b_emb  = (const float*)d_in[6];
    const float* W_q    = (const float*)d_in[7];
    const float* b_q    = (const float*)d_in[8];
    const float* W_k    = (const float*)d_in[9];
    const float* b_k    = (const float*)d_in[10];
    const float* W_eq   = (const float*)d_in[11];
    const float* b_eq   = (const float*)d_in[12];
    const float* W_ek   = (const float*)d_in[13];
    const float* b_ek   = (const float*)d_in[14];
    const float* W_ceq  = (const float*)d_in[15];
    const float* b_ceq  = (const float*)d_in[16];
    const float* W_cek  = (const float*)d_in[17];
    const float* b_cek  = (const float*)d_in[18];
    float* out = (float*)d_out;

    static cudaStream_t sA = nullptr, sB = nullptr;
    static cudaEvent_t evRoot, evPrep, evA, evB;
    if (!sA) {
        cudaStreamCreateWithFlags(&sA, cudaStreamNonBlocking);
        cudaStreamCreateWithFlags(&sB, cudaStreamNonBlocking);
        cudaEventCreateWithFlags(&evRoot, cudaEventDisableTiming);
        cudaEventCreateWithFlags(&evPrep, cudaEventDisableTiming);
        cudaEventCreateWithFlags(&evA,    cudaEventDisableTiming);
        cudaEventCreateWithFlags(&evB,    cudaEventDisableTiming);
    }

    // fork from the capture (default) stream
    cudaEventRecord(evRoot, 0);
    cudaStreamWaitEvent(sA, evRoot, 0);

    k_prep<<<129, 256, 0, sA>>>(W_emb, b_emb, W_q, b_q, W_k, b_k,
                                edge, cedge, W_eq, b_eq, W_ek, b_ek,
                                W_ceq, b_ceq, W_cek, b_cek);
    cudaEventRecord(evPrep, sA);
    cudaStreamWaitEvent(sB, evPrep, 0);

    // chain A: branch 0
    k_gextra<<<256, 256, 0, sA>>>(G, CG, x, 0);
    k_attn<<<1024, 256, 0, sA>>>(out, 0);
    cudaEventRecord(evA, sA);

    // chain B: branch 1
    k_gextra<<<256, 256, 0, sB>>>(G, CG, x, 1);
    k_attn<<<1024, 256, 0, sB>>>(out, 1);
    cudaEventRecord(evB, sB);

    // join back to the capture stream
    cudaStreamWaitEvent(0, evA, 0);
    cudaStreamWaitEvent(0, evB, 0);
}

// round 17
// speedup vs baseline: 1.0374x; 1.0374x over previous
#include <cuda_runtime.h>
#include <cstdint>

#define Bsz 8
#define Nn 1024
#define Ee 256
#define Dm 64
#define Hh 4
#define DH 16

// fold 1/sqrt(64) * log2(e) into gq so scores feed ex2 directly
#define QSCALE 0.180336880520712f

// ---------------- device scratch ----------------
__device__ float d_e [4][Bsz][Hh][Ee][DH];        // eq, ek, ceq, cek
__device__ float d_g [2][2][Bsz][Hh][DH][Nn];     // [branch][q|k][b][h][c][n]
// fused emb->q/k weights: [qk][i][64] at 0/64/128/192, biases [qk][64] at 256/320
__device__ float d_wfold[384];

// ---------------- K1: edge projections + weight folding ----------------
// grid 129 x 256: bid<128 edge rows; bid==128 computes fused q/k weights.
__global__ void __launch_bounds__(256)
k_prep(const float* __restrict__ W_emb, const float* __restrict__ b_emb,
       const float* __restrict__ W_q,   const float* __restrict__ b_q,
       const float* __restrict__ W_k,   const float* __restrict__ b_k,
       const float* __restrict__ edge,  const float* __restrict__ cedge,
       const float* __restrict__ W_eq,  const float* __restrict__ b_eq,
       const float* __restrict__ W_ek,  const float* __restrict__ b_ek,
       const float* __restrict__ W_ceq, const float* __restrict__ b_ceq,
       const float* __restrict__ W_cek, const float* __restrict__ b_cek) {
    int tid = threadIdx.x;

    if (blockIdx.x < 128) {
        __shared__ float sW4[1024];               // [4][16][16]
        __shared__ float sb4[64];                 // [4][16]
        {
            const float* Ws[4] = {W_eq, W_ek, W_ceq, W_cek};
            for (int l = tid; l < 1024; l += 256)
                sW4[l] = Ws[l >> 8][l & 255];
            if (tid < 64) {
                const float* Bs[4] = {b_eq, b_ek, b_ceq, b_cek};
                sb4[tid] = Bs[tid >> 4][tid & 15];
            }
        }
        __syncthreads();

        int i = blockIdx.x * 256 + tid;           // 0..32767
        int t = i >> 13;
        int r = i & 8191;
        const float* src = (t < 2 ? edge : cedge) + r * 16;
        float s[16];
#pragma unroll
        for (int j4 = 0; j4 < 4; ++j4) {
            float4 v = *(const float4*)(src + j4 * 4);
            s[j4 * 4 + 0] = v.x; s[j4 * 4 + 1] = v.y;
            s[j4 * 4 + 2] = v.z; s[j4 * 4 + 3] = v.w;
        }
        float acc[16];
#pragma unroll
        for (int cc = 0; cc < 16; ++cc) acc[cc] = sb4[t * 16 + cc];
#pragma unroll
        for (int j = 0; j < 16; ++j) {
            float sv = s[j];
#pragma unroll
            for (int cc = 0; cc < 16; ++cc)
                acc[cc] = fmaf(sv, sW4[t * 256 + j * 16 + cc], acc[cc]);
        }
        float* dst = (&d_e[0][0][0][0][0]) + (size_t)i * 16;
#pragma unroll
        for (int c4 = 0; c4 < 4; ++c4)
            *(float4*)(dst + c4 * 4) =
                make_float4(acc[c4 * 4], acc[c4 * 4 + 1], acc[c4 * 4 + 2], acc[c4 * 4 + 3]);
    } else {
        __shared__ float sWe[128];
        __shared__ float sbe[64];
        if (tid < 128) sWe[tid] = W_emb[tid];
        if (tid < 64)  sbe[tid] = b_emb[tid];
        __syncthreads();
        int c = tid & 63;
        int role = tid >> 6;                      // 0:(q,i0) 1:(q,i1) 2:(k,i0) 3:(k,i1)
        const float* W = (role < 2) ? W_q : W_k;
        int i = role & 1;
        float acc = 0.f;
#pragma unroll
        for (int j = 0; j < 64; ++j)
            acc = fmaf(sWe[i * 64 + j], W[j * 64 + c], acc);
        d_wfold[(role >> 1) * 128 + i * 64 + c] = acc;
        if ((role & 1) == 0) {
            const float* bb = (role == 0) ? b_q : b_k;
            float bacc = bb[c];
#pragma unroll
            for (int j = 0; j < 64; ++j)
                bacc = fmaf(sbe[j], W[j * 64 + c], bacc);
            d_wfold[256 + (role >> 1) * 64 + c] = bacc;
        }
    }
}

// ---------------- K3: gq/gk + div — ROUND-15 version (4 n/thread, prefetch) ----------------
// grid per branch: 8b * 16nt = 128 blocks; 256 threads = 16 c x 16 ns (4 n each).
__global__ void __launch_bounds__(256, 2)
k_gextra(const float* __restrict__ G, const float* __restrict__ CG,
         const float* __restrict__ x, int br) {
    int bid = blockIdx.x;
    int nt = bid & 15;  bid >>= 4;
    int b  = bid & 7;
    int tid = threadIdx.x;
    int c  = tid >> 4;          // 0..15
    int ns = tid & 15;          // 0..15 -> n = nbase + ns*4 + 0..3
    int nbase = nt * 64;

    const float* Gm  = (br ? CG : G) + (size_t)b * Ee * Nn;
    const float* eqb = &d_e[br * 2 + 0][b][0][0][0];   // [h][e][c], h-stride 4096
    const float* ekb = &d_e[br * 2 + 1][b][0][0][0];

    __shared__ float4 sg4[16][16];       // [ee][ns]
    __shared__ float  seq[4][16][16];    // [h][ee][c]  = 256 float4
    __shared__ float  sek[4][16][16];
    __shared__ float  swf[384];          // fused weights + biases
    __shared__ float  sx[128];           // x[b][nbase..nbase+63][2]
    float4* sq4 = (float4*)&seq[0][0][0];
    float4* sk4 = (float4*)&sek[0][0][0];

    if (tid < 128) sx[tid] = x[((size_t)b * Nn + nbase) * 2 + tid];
    for (int i = tid; i < 384; i += 256) swf[i] = d_wfold[i];

    int ge = tid >> 4, gn = tid & 15;
    int h4 = tid >> 6, ee4 = (tid & 63) >> 2, c4 = tid & 3;
    const float* gsrc = Gm + (size_t)ge * Nn + nbase + gn * 4;
    size_t eoff = (size_t)(h4 * Ee + ee4) * DH + c4 * 4;

    float aq[4][4], ak[4][4];            // [h][n]
#pragma unroll
    for (int h = 0; h < 4; ++h)
#pragma unroll
        for (int j = 0; j < 4; ++j) { aq[h][j] = 0.f; ak[h][j] = 0.f; }
    float gs0 = 0.f, gs1 = 0.f, gs2 = 0.f, gs3 = 0.f;

    // preload tile 0
    float4 gpre = *(const float4*)(gsrc);
    float4 qpre = *(const float4*)(eqb + eoff);
    float4 kpre = *(const float4*)(ekb + eoff);

#pragma unroll 1
    for (int e0 = 0; e0 < Ee; e0 += 16) {
        sg4[ge][gn] = gpre;
        sq4[tid] = qpre;
        sk4[tid] = kpre;
        __syncthreads();
        if (e0 + 16 < Ee) {              // prefetch next tile (overlaps compute)
            gpre = *(const float4*)(gsrc + (size_t)(e0 + 16) * Nn);
            qpre = *(const float4*)(eqb + eoff + (size_t)(e0 + 16) * DH);
            kpre = *(const float4*)(ekb + eoff + (size_t)(e0 + 16) * DH);
        }
#pragma unroll
        for (int ee = 0; ee < 16; ++ee) {
            float4 g = sg4[ee][ns];
            gs0 += g.x; gs1 += g.y; gs2 += g.z; gs3 += g.w;
#pragma unroll
            for (int h = 0; h < 4; ++h) {
                float eqv = seq[h][ee][c];
                float ekv = sek[h][ee][c];
                aq[h][0] = fmaf(g.x, eqv, aq[h][0]);
                aq[h][1] = fmaf(g.y, eqv, aq[h][1]);
                aq[h][2] = fmaf(g.z, eqv, aq[h][2]);
                aq[h][3] = fmaf(g.w, eqv, aq[h][3]);
                ak[h][0] = fmaf(g.x, ekv, ak[h][0]);
                ak[h][1] = fmaf(g.y, ekv, ak[h][1]);
                ak[h][2] = fmaf(g.z, ekv, ak[h][2]);
                ak[h][3] = fmaf(g.w, ekv, ak[h][3]);
            }
        }
        __syncthreads();
    }
    float rd0 = 1.0f / gs0, rd1 = 1.0f / gs1, rd2 = 1.0f / gs2, rd3 = 1.0f / gs3;
    int n0 = nbase + ns * 4;

    float x0[4], x1[4];
#pragma unroll
    for (int nn = 0; nn < 4; ++nn) {
        x0[nn] = sx[(ns * 4 + nn) * 2 + 0];
        x1[nn] = sx[(ns * 4 + nn) * 2 + 1];
    }
#pragma unroll
    for (int h = 0; h < 4; ++h) {
        int ch = h * 16 + c;
        float wq0 = swf[ch],       wq1 = swf[64 + ch];
        float wk0 = swf[128 + ch], wk1 = swf[192 + ch];
        float bq  = swf[256 + ch], bk  = swf[320 + ch];
        float4 oq, ok;
        oq.x = (fmaf(x0[0], wq0, fmaf(x1[0], wq1, bq)) + aq[h][0] * rd0) * QSCALE;
        oq.y = (fmaf(x0[1], wq0, fmaf(x1[1], wq1, bq)) + aq[h][1] * rd1) * QSCALE;
        oq.z = (fmaf(x0[2], wq0, fmaf(x1[2], wq1, bq)) + aq[h][2] * rd2) * QSCALE;
        oq.w = (fmaf(x0[3], wq0, fmaf(x1[3], wq1, bq)) + aq[h][3] * rd3) * QSCALE;
        ok.x = (fmaf(x0[0], wk0, fmaf(x1[0], wk1, bk)) + ak[h][0] * rd0);
        ok.y = (fmaf(x0[1], wk0, fmaf(x1[1], wk1, bk)) + ak[h][1] * rd1);
        ok.z = (fmaf(x0[2], wk0, fmaf(x1[2], wk1, bk)) + ak[h][2] * rd2);
        ok.w = (fmaf(x0[3], wk0, fmaf(x1[3], wk1, bk)) + ak[h][3] * rd3);
        *(float4*)&d_g[br][0][b][h][c][n0] = oq;
        *(float4*)&d_g[br][1][b][h][c][n0] = ok;
    }
}

// ---------------- K4: scores + softmax — RCHUNK 64 (halved gk reloads) ----------------
#define RCHUNK 64
__global__ void __launch_bounds__(256, 2)
k_attn(float* __restrict__ out, int br) {
    int bid = blockIdx.x;
    int chunk = bid & 15;  bid >>= 4;
    int h     = bid & 3;   bid >>= 2;
    int b     = bid & 7;
    int rbase = chunk * RCHUNK;

    const float* gq = &d_g[br][0][b][h][0][0];   // [c][n]
    const float* gk = &d_g[br][1][b][h][0][0];   // [c][n]

    __shared__ float sq[RCHUNK][20];
    __shared__ float spart[2][8][4];             // parity double-buffered

    int tid  = threadIdx.x;
    int warp = tid >> 5, lane = tid & 31;
    int col0 = warp * 128 + lane * 4;

    float4 kk[16];
#pragma unroll
    for (int c = 0; c < 16; ++c)
        kk[c] = *(const float4*)(gk + c * Nn + col0);

    for (int i = tid; i < RCHUNK * 16; i += 256) {
        int c = i >> 6, r = i & 63;
        sq[r][c] = gq[c * Nn + rbase + r];
    }
    __syncthreads();

    size_t obase = ((((size_t)br * Bsz + b) * Hh + h) * Nn + rbase) * (size_t)Nn;

#pragma unroll 1
    for (int wv = 0; wv < RCHUNK / 4; ++wv) {
        int r0 = wv * 4;
        float4 ex[4];
        float part[4];
#pragma unroll
        for (int rr = 0; rr < 4; ++rr) {
            const float* qp = &sq[r0 + rr][0];
            float4 qa = *(const float4*)(qp + 0);
            float4 qb = *(const float4*)(qp + 4);
            float4 qc = *(const float4*)(qp + 8);
            float4 qd = *(const float4*)(qp + 12);
            float qv[16] = {qa.x, qa.y, qa.z, qa.w, qb.x, qb.y, qb.z, qb.w,
                            qc.x, qc.y, qc.z, qc.w, qd.x, qd.y, qd.z, qd.w};
            float s0 = 0.f, s1 = 0.f, s2 = 0.f, s3 = 0.f;
#pragma unroll
            for (int c = 0; c < 16; ++c) {
                s0 = fmaf(qv[c], kk[c].x, s0);
                s1 = fmaf(qv[c], kk[c].y, s1);
                s2 = fmaf(qv[c], kk[c].z, s2);
                s3 = fmaf(qv[c], kk[c].w, s3);
            }
            float e0, e1, e2, e3;
            asm("ex2.approx.f32 %0, %1;" : "=f"(e0) : "f"(s0));
            asm("ex2.approx.f32 %0, %1;" : "=f"(e1) : "f"(s1));
            asm("ex2.approx.f32 %0, %1;" : "=f"(e2) : "f"(s2));
            asm("ex2.approx.f32 %0, %1;" : "=f"(e3) : "f"(s3));
            ex[rr] = make_float4(e0, e1, e2, e3);
            part[rr] = (e0 + e1) + (e2 + e3);
        }
#pragma unroll
        for (int o = 16; o; o >>= 1)
#pragma unroll
            for (int rr = 0; rr < 4; ++rr)
                part[rr] += __shfl_xor_sync(0xffffffffu, part[rr], o);
        int par = wv & 1;
        if (lane == 0) {
#pragma unroll
            for (int rr = 0; rr < 4; ++rr) spart[par][warp][rr] = part[rr];
        }
        __syncthreads();                         // single barrier per wave
#pragma unroll
        for (int rr = 0; rr < 4; ++rr) {
            float v = spart[par][lane & 7][rr];  // 8-way broadcast LDS
            v += __shfl_xor_sync(0xffffffffu, v, 1);
            v += __shfl_xor_sync(0xffffffffu, v, 2);
            v += __shfl_xor_sync(0xffffffffu, v, 4);
            float iv = 1.0f / v;
            float4 o4 = ex[rr];
            o4.x *= iv; o4.y *= iv; o4.z *= iv; o4.w *= iv;
            __stcs((float4*)(out + obase + (size_t)(r0 + rr) * Nn + col0), o4);
        }
    }
}

// ---------------- launcher: dual-stream branch pipeline ----------------
extern "C" void kernel_launch(void* const* d_in, const int* in_sizes, int n_in,
                              void* d_out, int out_size) {
    const float* x      = (const float*)d_in[0];
    const float* edge   = (const float*)d_in[1];
    const float* cedge  = (const float*)d_in[2];
    const float* G      = (const float*)d_in[3];
    const float* CG     = (const float*)d_in[4];
    const float* W_emb  = (const float*)d_in[5];
    const float* b_emb  = (const float*)d_in[6];
    const float* W_q    = (const float*)d_in[7];
    const float* b_q    = (const float*)d_in[8];
    const float* W_k    = (const float*)d_in[9];
    const float* b_k    = (const float*)d_in[10];
    const float* W_eq   = (const float*)d_in[11];
    const float* b_eq   = (const float*)d_in[12];
    const float* W_ek   = (const float*)d_in[13];
    const float* b_ek   = (const float*)d_in[14];
    const float* W_ceq  = (const float*)d_in[15];
    const float* b_ceq  = (const float*)d_in[16];
    const float* W_cek  = (const float*)d_in[17];
    const float* b_cek  = (const float*)d_in[18];
    float* out = (float*)d_out;

    static cudaStream_t sA = nullptr, sB = nullptr;
    static cudaEvent_t evRoot, evPrep, evA, evB;
    if (!sA) {
        cudaStreamCreateWithFlags(&sA, cudaStreamNonBlocking);
        cudaStreamCreateWithFlags(&sB, cudaStreamNonBlocking);
        cudaEventCreateWithFlags(&evRoot, cudaEventDisableTiming);
        cudaEventCreateWithFlags(&evPrep, cudaEventDisableTiming);
        cudaEventCreateWithFlags(&evA,    cudaEventDisableTiming);
        cudaEventCreateWithFlags(&evB,    cudaEventDisableTiming);
    }

    // fork from the capture (default) stream
    cudaEventRecord(evRoot, 0);
    cudaStreamWaitEvent(sA, evRoot, 0);

    k_prep<<<129, 256, 0, sA>>>(W_emb, b_emb, W_q, b_q, W_k, b_k,
                                edge, cedge, W_eq, b_eq, W_ek, b_ek,
                                W_ceq, b_ceq, W_cek, b_cek);
    cudaEventRecord(evPrep, sA);
    cudaStreamWaitEvent(sB, evPrep, 0);

    // chain A: branch 0
    k_gextra<<<128, 256, 0, sA>>>(G, CG, x, 0);
    k_attn<<<512, 256, 0, sA>>>(out, 0);
    cudaEventRecord(evA, sA);

    // chain B: branch 1
    k_gextra<<<128, 256, 0, sB>>>(G, CG, x, 1);
    k_attn<<<512, 256, 0, sB>>>(out, 1);
    cudaEventRecord(evB, sB);

    // join back to the capture stream
    cudaStreamWaitEvent(0, evA, 0);
    cudaStreamWaitEvent(0, evB, 0);
}